// round 6
// baseline (speedup 1.0000x reference)
#include <cuda_runtime.h>
#include <cuda_bf16.h>
#include <cstdint>

// BlockAttnRes: per-token block attention over N=9 source rows of D=512.
//   score_n = dot(src_n, w) / sqrt(mean(src_n^2)+1e-6),  alpha = softmax(score),
//   h = sum_n alpha_n * src_n.
//
// R6: persistent grid + L2 PREFETCH of the next token. prefetch.global.L2
// costs no registers (R4's failure) and no smem (R2/R5's failure): DRAM->L2
// read-ahead streams during the compute phase, so dram__cycles_active's 20%
// idle holes get filled; the next iteration's LDGs hit L2 (~240cyc).
// Compute stays register-resident (R1/R3 skeleton, <=64 regs, 8 CTAs/SM).
// alpha[] eliminated (scores recomputed from broadcast smem) to hold regs.

#define NN 9
#define DD 512
#define THREADS 128
#define CTAS_PER_SM 8
#define GRID (152 * CTAS_PER_SM)
#define TILE_BYTES (NN * DD * 4)   // 18432 -> 144 lines of 128B

__global__ __launch_bounds__(THREADS, CTAS_PER_SM)
void blockattn_kernel(const float* __restrict__ src,
                      const float* __restrict__ queries,
                      const int*   __restrict__ layer_idx,
                      float*       __restrict__ out,
                      int tokens)
{
    __shared__ float s_red[2][2][NN][4];   // [parity][ss/dt][row][warp]

    const int tid  = threadIdx.x;
    const int lane = tid & 31;
    const int warp = tid >> 5;
    const int G    = gridDim.x;

    const int li = __ldg(layer_idx);
    const float4 w4 = __ldg(reinterpret_cast<const float4*>(queries + (long long)li * DD) + tid);

    const float4* srcv = reinterpret_cast<const float4*>(src);
    float4*       outv = reinterpret_cast<float4*>(out);

    long long t = blockIdx.x;

    // ---- Prologue: warm L2 for this CTA's first token ----
    if (t < tokens) {
        const char* pf = reinterpret_cast<const char*>(srcv + t * (NN * DD / 4));
        asm volatile("prefetch.global.L2 [%0];" :: "l"(pf + (size_t)tid * 128));
        if (tid < (TILE_BYTES / 128 - THREADS))
            asm volatile("prefetch.global.L2 [%0];" :: "l"(pf + (size_t)(THREADS + tid) * 128));
    }

    int p = 0;
    for (; t < tokens; t += G, p ^= 1) {
        const float4* base = srcv + t * (NN * DD / 4);

        // ---- Load all 9 rows into registers (L2-hot from prior prefetch) ----
        float4 v[NN];
#pragma unroll
        for (int n = 0; n < NN; n++)
            v[n] = base[n * (DD / 4) + tid];

        // ---- Prefetch NEXT token into L2 (streams from DRAM during compute) ----
        const long long tn = t + G;
        if (tn < tokens) {
            const char* pf = reinterpret_cast<const char*>(srcv + tn * (NN * DD / 4));
            asm volatile("prefetch.global.L2 [%0];" :: "l"(pf + (size_t)tid * 128));
            if (tid < (TILE_BYTES / 128 - THREADS))
                asm volatile("prefetch.global.L2 [%0];" :: "l"(pf + (size_t)(THREADS + tid) * 128));
        }

        // ---- Per-row partials: sumsq & dot, warp-reduce, stash ----
#pragma unroll
        for (int n = 0; n < NN; n++) {
            const float4 a = v[n];
            float ssn = a.x * a.x + a.y * a.y + a.z * a.z + a.w * a.w;
            float dtn = a.x * w4.x + a.y * w4.y + a.z * w4.z + a.w * w4.w;
#pragma unroll
            for (int o = 16; o > 0; o >>= 1) {
                ssn += __shfl_xor_sync(0xffffffffu, ssn, o);
                dtn += __shfl_xor_sync(0xffffffffu, dtn, o);
            }
            if (lane == 0) {
                s_red[p][0][n][warp] = ssn;
                s_red[p][1][n][warp] = dtn;
            }
        }
        __syncthreads();   // single barrier per iteration (parity buffers)

        // ---- Pass 1 over smem partials: max score (no alpha[] kept) ----
        float mx = -3.4e38f;
#pragma unroll
        for (int n = 0; n < NN; n++) {
            const float S  = s_red[p][0][n][0] + s_red[p][0][n][1]
                           + s_red[p][0][n][2] + s_red[p][0][n][3];
            const float Dt = s_red[p][1][n][0] + s_red[p][1][n][1]
                           + s_red[p][1][n][2] + s_red[p][1][n][3];
            mx = fmaxf(mx, Dt * rsqrtf(S * (1.0f / DD) + 1e-6f));
        }

        // ---- Pass 2: fuse exp + weighted accumulation; normalize at end ----
        float4 o = make_float4(0.f, 0.f, 0.f, 0.f);
        float sum = 0.0f;
#pragma unroll
        for (int n = 0; n < NN; n++) {
            const float S  = s_red[p][0][n][0] + s_red[p][0][n][1]
                           + s_red[p][0][n][2] + s_red[p][0][n][3];
            const float Dt = s_red[p][1][n][0] + s_red[p][1][n][1]
                           + s_red[p][1][n][2] + s_red[p][1][n][3];
            const float e = __expf(Dt * rsqrtf(S * (1.0f / DD) + 1e-6f) - mx);
            sum += e;
            o.x += e * v[n].x;
            o.y += e * v[n].y;
            o.z += e * v[n].z;
            o.w += e * v[n].w;
        }
        const float inv = 1.0f / sum;
        o.x *= inv; o.y *= inv; o.z *= inv; o.w *= inv;

        __stcs(outv + t * (DD / 4) + tid, o);
    }
}

extern "C" void kernel_launch(void* const* d_in, const int* in_sizes, int n_in,
                              void* d_out, int out_size)
{
    const float* src     = (const float*)d_in[0];
    const float* queries = (const float*)d_in[1];
    const int*   lidx    = (const int*)d_in[2];
    float*       out     = (float*)d_out;

    const int tokens = in_sizes[0] / (NN * DD);   // B*T = 32768
    const int grid = (tokens < GRID) ? tokens : GRID;
    blockattn_kernel<<<grid, THREADS>>>(src, queries, lidx, out, tokens);
}